// round 2
// baseline (speedup 1.0000x reference)
#include <cuda_runtime.h>
#include <cuda_bf16.h>

// Output layout: [muTE (N floats)] ++ [M (N*N floats, row-major)]
// h = 0 (hunter), p = 1 (prey).
// M is zero except rows/cols 0 and 1 (see Round-0 derivation).

#define TPB 256u
#define VPT 4u   // float4 slots per thread

__device__ __forceinline__ float4 special_value(unsigned int off,
                                                const float* __restrict__ mu,
                                                const float* __restrict__ var,
                                                unsigned int N,
                                                unsigned int i,
                                                unsigned int j) {
    float4 r = make_float4(0.f, 0.f, 0.f, 0.f);

    if (off < N) {
        // muTE region: only the first float4 is nonzero
        if (off == 0u) {
            float hp = __ldg(&var[1]);
            r.x = hp;
            r.y = -hp;
        }
        return r;
    }

    float mu0   = __ldg(&mu[0]);
    float mu1   = __ldg(&mu[1]);
    float var01 = __ldg(&var[1]);
    float c = var01 - 2.f * mu0 * mu1;

    if (i < 2u) {
        // Rows 0 (sign +) and 1 (sign -): value = s * v[j..j+3]
        float s = (i == 0u) ? 1.f : -1.f;
        float vv[4];
        #pragma unroll
        for (int q = 0; q < 4; ++q) {
            unsigned int jj = j + (unsigned int)q;
            float vj;
            if (jj < 2u) {
                vj = 0.f;   // loop excludes j == prey, j == hunter
            } else {
                vj = fmaf(__ldg(&mu[jj]), c,
                      fmaf(mu1, __ldg(&var[jj]),         // var[0, jj]
                           mu0 * __ldg(&var[N + jj])));  // var[1, jj]
            }
            vv[q] = s * vj;
        }
        r.x = vv[0]; r.y = vv[1]; r.z = vv[2]; r.w = vv[3];

        if (j == 0u) {
            // Special 2x2 block
            float var00 = __ldg(&var[0]);
            float var11 = __ldg(&var[N + 1]);
            float hp = var01;
            float n3_pph = -2.f * mu1 * mu1 * mu0 + 2.f * mu1 * var01 + mu0 * var11;
            float n3_hhp = -2.f * mu0 * mu0 * mu1 + 2.f * mu0 * var01 + mu1 * var00;
            float n3_hpp = -2.f * mu0 * mu1 * mu1 + mu0 * var11 + 2.f * mu1 * var01;
            float chp = -n3_hhp + n3_hpp - hp;
            if (i == 0u) {
                r.x = 2.f * n3_hhp + hp;   // (0,0)
                r.y = chp;                 // (0,1)
            } else {
                r.x = chp;                 // (1,0)
                r.y = -2.f * n3_pph + hp;  // (1,1)
            }
        }
    } else {
        // j == 0, rows i >= 2: columns 0/1 hold +v[i], -v[i]
        float vi = fmaf(__ldg(&mu[i]), c,
                    fmaf(mu1, __ldg(&var[i]),            // var[0, i]
                         mu0 * __ldg(&var[N + i])));     // var[1, i]
        r.x = vi;
        r.y = -vi;
    }
    return r;
}

__global__ void eatrxn_fused_kernel(const float* __restrict__ mu,
                                    const float* __restrict__ var,
                                    float* __restrict__ out,
                                    unsigned int total4,
                                    unsigned int N,
                                    unsigned int shift,
                                    unsigned int mask) {
    unsigned int base = blockIdx.x * (TPB * VPT) + threadIdx.x;
    float4* __restrict__ out4 = reinterpret_cast<float4*>(out);

    #pragma unroll
    for (unsigned int k = 0; k < VPT; ++k) {
        unsigned int t = base + k * TPB;
        if (t >= total4) break;
        unsigned int off = t << 2;            // element offset of this float4
        unsigned int m = off - N;             // wraps when off < N (harmless, see below)
        unsigned int i = m >> shift;          // row within M
        unsigned int j = m & mask;            // col within M (float4 spans j..j+3)

        float4 r = make_float4(0.f, 0.f, 0.f, 0.f);
        // Rare-path predicate. For off < N, (off < N) dominates; the wrapped
        // i/j are only consumed inside special_value under correct guards.
        if ((off < N) | (i < 2u) | (j == 0u)) {
            r = special_value(off, mu, var, N, i, j);
        }
        __stcs(&out4[t], r);   // streaming store: write-once, never re-read
    }
}

extern "C" void kernel_launch(void* const* d_in, const int* in_sizes, int n_in,
                              void* d_out, int out_size) {
    const float* mu  = (const float*)d_in[0];
    const float* var = (const float*)d_in[1];
    float* out = (float*)d_out;

    unsigned int N = (unsigned int)in_sizes[0];   // 8192
    unsigned int shift = 0;
    while ((1u << shift) < N) ++shift;            // N power of two -> 13
    unsigned int mask = N - 1u;

    unsigned int total4 = (unsigned int)(out_size / 4);

    unsigned int per_block = TPB * VPT;
    unsigned int blocks = (total4 + per_block - 1) / per_block;
    eatrxn_fused_kernel<<<blocks, TPB>>>(mu, var, out, total4, N, shift, mask);
    // out_size for this problem is a multiple of 4 (N and N*N both are), so no
    // scalar tail is needed; total4*4 == out_size.
}